// round 9
// baseline (speedup 1.0000x reference)
#include <cuda_runtime.h>
#include <cuda_bf16.h>
#include <cstdint>
#include <math.h>

// Problem shape (fixed by setup_inputs)
#define Bn 2048
#define Kn 256
#define Dn 512

// bf16 staging buffers (__device__ globals: allocation-free)
__device__ __nv_bfloat16 g_bmat[Kn * 1024];  // [k][ 0..511: bw | 512..1023: -2*bw*c ]
__device__ __nv_bfloat16 g_rbf [Bn * Kn];    // rbf result, K-major for GEMM2
__device__ __nv_bfloat16 g_wt  [Dn * Kn];    // softplus(W) transposed: [d][k]
__device__ float         g_ck  [Kn];         // sum_d bw*c^2

// ---------------------------------------------------------------------------
// Helpers (arch-generic: ldmatrix / mma.sync / cp.async — NO tcgen05, the
// harness PTX stage targets plain compute_103)
// ---------------------------------------------------------------------------
__device__ __forceinline__ uint32_t s2u(const void* p) {
    uint32_t a;
    asm("{ .reg .u64 t; cvta.to.shared.u64 t, %1; cvt.u32.u64 %0, t; }"
        : "=r"(a) : "l"(p));
    return a;
}
#define SW128(o) ((o) ^ (((o) >> 3) & 0x70))

__device__ __forceinline__ void cp16(uint32_t s, const void* g) {
    asm volatile("cp.async.cg.shared.global [%0], [%1], 16;" :: "r"(s), "l"(g));
}

__device__ __forceinline__ void ldsm4(uint32_t* r, uint32_t addr) {
    asm volatile("ldmatrix.sync.aligned.m8n8.x4.shared.b16 {%0,%1,%2,%3}, [%4];"
                 : "=r"(r[0]), "=r"(r[1]), "=r"(r[2]), "=r"(r[3]) : "r"(addr));
}

__device__ __forceinline__ void mma16816(float* c, const uint32_t* a, const uint32_t* b) {
    asm volatile(
        "mma.sync.aligned.m16n8k16.row.col.f32.bf16.bf16.f32 "
        "{%0,%1,%2,%3}, {%4,%5,%6,%7}, {%8,%9}, {%0,%1,%2,%3};"
        : "+f"(c[0]), "+f"(c[1]), "+f"(c[2]), "+f"(c[3])
        : "r"(a[0]), "r"(a[1]), "r"(a[2]), "r"(a[3]), "r"(b[0]), "r"(b[1]));
}

__device__ __forceinline__ uint32_t bits2(__nv_bfloat162 v) {
    return *(uint32_t*)&v;
}

// ---------------------------------------------------------------------------
// Prep (small now): 160 blocks x 256 threads.
//   blocks [0,32):   B-matrix build + ck (16 elems/thread, 1 warp per k-row)
//   blocks [32,160): W softplus + 32x32 transpose
// ---------------------------------------------------------------------------
__global__ void __launch_bounds__(256)
prep_all(const float* __restrict__ centers, const float* __restrict__ bandwidths,
         const float* __restrict__ raw) {
    const int bid = blockIdx.x, tid = threadIdx.x;

    if (bid < 32) {                          // ---- prepB + ck ----
        const int e = (bid * 256 + tid) * 16;
        const int k = e >> 9;
        const int d = e & 511;
        const float4* sb = (const float4*)(bandwidths + e);
        const float4* sc = (const float4*)(centers + e);
        float4 b0 = sb[0], b1 = sb[1], b2 = sb[2], b3 = sb[3];
        float4 c0 = sc[0], c1 = sc[1], c2 = sc[2], c3 = sc[3];
        uint4 wb0, wb1, wc0, wc1;
        wb0.x = bits2(__floats2bfloat162_rn(b0.x, b0.y));
        wb0.y = bits2(__floats2bfloat162_rn(b0.z, b0.w));
        wb0.z = bits2(__floats2bfloat162_rn(b1.x, b1.y));
        wb0.w = bits2(__floats2bfloat162_rn(b1.z, b1.w));
        wb1.x = bits2(__floats2bfloat162_rn(b2.x, b2.y));
        wb1.y = bits2(__floats2bfloat162_rn(b2.z, b2.w));
        wb1.z = bits2(__floats2bfloat162_rn(b3.x, b3.y));
        wb1.w = bits2(__floats2bfloat162_rn(b3.z, b3.w));
        wc0.x = bits2(__floats2bfloat162_rn(-2.0f * b0.x * c0.x, -2.0f * b0.y * c0.y));
        wc0.y = bits2(__floats2bfloat162_rn(-2.0f * b0.z * c0.z, -2.0f * b0.w * c0.w));
        wc0.z = bits2(__floats2bfloat162_rn(-2.0f * b1.x * c1.x, -2.0f * b1.y * c1.y));
        wc0.w = bits2(__floats2bfloat162_rn(-2.0f * b1.z * c1.z, -2.0f * b1.w * c1.w));
        wc1.x = bits2(__floats2bfloat162_rn(-2.0f * b2.x * c2.x, -2.0f * b2.y * c2.y));
        wc1.y = bits2(__floats2bfloat162_rn(-2.0f * b2.z * c2.z, -2.0f * b2.w * c2.w));
        wc1.z = bits2(__floats2bfloat162_rn(-2.0f * b3.x * c3.x, -2.0f * b3.y * c3.y));
        wc1.w = bits2(__floats2bfloat162_rn(-2.0f * b3.z * c3.z, -2.0f * b3.w * c3.w));
        uint4* db = (uint4*)&g_bmat[k * 1024 + d];
        uint4* dc = (uint4*)&g_bmat[k * 1024 + 512 + d];
        db[0] = wb0;  db[1] = wb1;
        dc[0] = wc0;  dc[1] = wc1;
        float s = b0.x * c0.x * c0.x + b0.y * c0.y * c0.y
                + b0.z * c0.z * c0.z + b0.w * c0.w * c0.w
                + b1.x * c1.x * c1.x + b1.y * c1.y * c1.y
                + b1.z * c1.z * c1.z + b1.w * c1.w * c1.w
                + b2.x * c2.x * c2.x + b2.y * c2.y * c2.y
                + b2.z * c2.z * c2.z + b2.w * c2.w * c2.w
                + b3.x * c3.x * c3.x + b3.y * c3.y * c3.y
                + b3.z * c3.z * c3.z + b3.w * c3.w * c3.w;
        #pragma unroll
        for (int o = 16; o > 0; o >>= 1)
            s += __shfl_down_sync(0xffffffffu, s, o);
        if ((tid & 31) == 0) g_ck[k] = s;
        return;
    }

    {                                        // ---- prepW ----
        const int t2 = bid - 32;
        const int d0 = (t2 & 15) * 32, k0 = (t2 >> 4) * 32;
        const int tx = tid & 31, ty = tid >> 5;          // 32 x 8
        __shared__ float t[32][33];
        #pragma unroll
        for (int jj = 0; jj < 4; jj++) {
            int k = k0 + ty + jj * 8;
            float r = raw[k * Dn + d0 + tx];
            t[ty + jj * 8][tx] = fmaxf(r, 0.0f) + __logf(1.0f + __expf(-fabsf(r)));
        }
        __syncthreads();
        #pragma unroll
        for (int jj = 0; jj < 4; jj++) {
            int d = d0 + ty + jj * 8;
            g_wt[d * Kn + k0 + tx] = __float2bfloat16(t[tx][ty + jj * 8]);
        }
    }
}

// ---------------------------------------------------------------------------
// G1, fused-conversion GEMM: dist[64,64] = [x^2|x] x [bw|cw]^T over D=512.
// 256 threads / 8 warps, warp grid 2(M) x 4(N), warp tile 32x16.
// Per d-pair (64 d-cols): x tile loaded fp32 from global into regs (issued
// during previous pair's compute), converted to x^2/x bf16 smem tiles
// (2-stage); bw/cw tiles via cp.async (3-stage). One barrier per pair.
// Epilogue: exp(-0.5*(dist+ck)) -> bf16 g_rbf. All warps own output rows.
// SMEM: A 2x16KB + B 3x16KB = 80KB.
// ---------------------------------------------------------------------------
#define G1_BBASE 32768
#define G1_SMEM  (32768 + 3 * 16384)   // 81920

__global__ void __launch_bounds__(256)
g1_kern(const float* __restrict__ x) {
    extern __shared__ char sm[];
    const uint32_t T0 = s2u(sm);
    const int tid = threadIdx.x, wid = tid >> 5, l = tid & 31;
    const int m0 = blockIdx.x * 64, n0 = blockIdx.y * 64;
    const int wm = wid & 1, wn = wid >> 1;

    const int lr = l & 7, sel = l >> 3;
    const int a_row = wm * 32 + (sel & 1) * 8 + lr;       // + mi*16
    const uint32_t a_kb = (uint32_t)((sel >> 1) * 16);    // + ks*32
    const int b_row = wn * 16 + (sel >> 1) * 8 + lr;
    const uint32_t b_kb = (uint32_t)((sel & 1) * 16);

    // x loader mapping: thread -> (row, 16-col segment)
    const int xr = tid >> 2, xc = (tid & 3) * 16;
    const float* xbase = x + (size_t)(m0 + xr) * Dn + xc;
    const uint32_t sts_o0 = SW128((uint32_t)(xr * 128 + xc * 2));
    const uint32_t sts_o1 = SW128((uint32_t)(xr * 128 + xc * 2 + 16));

    // B loader mapping
    const int br = tid >> 3, bc = tid & 7;
    const uint32_t cp_off = SW128((uint32_t)(br * 128 + bc * 16));
    const __nv_bfloat16* gb_row = g_bmat + (size_t)(n0 + br) * 1024 + bc * 8;

    #define CPB(p) do {                                                      \
        uint32_t _b = T0 + G1_BBASE + ((p) % 3) * 16384;                     \
        const __nv_bfloat16* _g = gb_row + (p) * 64;                         \
        cp16(_b        + cp_off, _g);                                        \
        cp16(_b + 8192 + cp_off, _g + 512);                                  \
        asm volatile("cp.async.commit_group;");                              \
    } while (0)

    float4 v0, v1, v2, v3;
    #define LDX(p) do {                                                      \
        const float4* _s = (const float4*)(xbase + (p) * 64);                \
        v0 = _s[0]; v1 = _s[1]; v2 = _s[2]; v3 = _s[3];                      \
    } while (0)

    float acc[2][2][4];
    #pragma unroll
    for (int mi = 0; mi < 2; mi++)
        #pragma unroll
        for (int nj = 0; nj < 2; nj++)
            #pragma unroll
            for (int e = 0; e < 4; e++) acc[mi][nj][e] = 0.0f;

    LDX(0);
    CPB(0);
    CPB(1);

    for (int p = 0; p < 8; p++) {
        const int s = p & 1;
        if (p < 6) asm volatile("cp.async.wait_group 1;");
        else       asm volatile("cp.async.wait_group 0;");

        // convert + STS x^2 / x tiles into A stage s
        {
            uint4 q0, q1, w0, w1;
            q0.x = bits2(__floats2bfloat162_rn(v0.x * v0.x, v0.y * v0.y));
            q0.y = bits2(__floats2bfloat162_rn(v0.z * v0.z, v0.w * v0.w));
            q0.z = bits2(__floats2bfloat162_rn(v1.x * v1.x, v1.y * v1.y));
            q0.w = bits2(__floats2bfloat162_rn(v1.z * v1.z, v1.w * v1.w));
            q1.x = bits2(__floats2bfloat162_rn(v2.x * v2.x, v2.y * v2.y));
            q1.y = bits2(__floats2bfloat162_rn(v2.z * v2.z, v2.w * v2.w));
            q1.z = bits2(__floats2bfloat162_rn(v3.x * v3.x, v3.y * v3.y));
            q1.w = bits2(__floats2bfloat162_rn(v3.z * v3.z, v3.w * v3.w));
            w0.x = bits2(__floats2bfloat162_rn(v0.x, v0.y));
            w0.y = bits2(__floats2bfloat162_rn(v0.z, v0.w));
            w0.z = bits2(__floats2bfloat162_rn(v1.x, v1.y));
            w0.w = bits2(__floats2bfloat162_rn(v1.z, v1.w));
            w1.x = bits2(__floats2bfloat162_rn(v2.x, v2.y));
            w1.y = bits2(__floats2bfloat162_rn(v2.z, v2.w));
            w1.z = bits2(__floats2bfloat162_rn(v3.x, v3.y));
            w1.w = bits2(__floats2bfloat162_rn(v3.z, v3.w));
            char* asq = sm + s * 16384;
            char* ax  = asq + 8192;
            *(uint4*)(asq + sts_o0) = q0;  *(uint4*)(asq + sts_o1) = q1;
            *(uint4*)(ax  + sts_o0) = w0;  *(uint4*)(ax  + sts_o1) = w1;
        }
        __syncthreads();     // stage s tiles visible; pair p-1 compute done

        if (p < 7) LDX(p + 1);
        if (p < 6) CPB(p + 2);

        const uint32_t asq = T0 + s * 16384;
        const uint32_t ax  = asq + 8192;
        const uint32_t bw  = T0 + G1_BBASE + (p % 3) * 16384;
        const uint32_t cw  = bw + 8192;

        #pragma unroll
        for (int half = 0; half < 2; half++) {
            const uint32_t sa  = half ? ax : asq;
            const uint32_t sbb = half ? cw : bw;
            #pragma unroll
            for (int ks = 0; ks < 4; ks++) {
                uint32_t a[2][4], b[4];
                #pragma unroll
                for (int mi = 0; mi < 2; mi++)
                    ldsm4(a[mi], sa + SW128((uint32_t)((a_row + mi * 16) * 128)
                                            + (uint32_t)(ks * 32) + a_kb));
                ldsm4(b, sbb + SW128((uint32_t)(b_row * 128)
                                     + (uint32_t)(ks * 32) + b_kb));
                #pragma unroll
                for (int mi = 0; mi < 2; mi++)
                    #pragma unroll
                    for (int nj = 0; nj < 2; nj++)
                        mma16816(acc[mi][nj], a[mi], &b[nj * 2]);
            }
        }
        __syncthreads();     // compute p done before stage s overwrite @ p+2
    }
    #undef CPB
    #undef LDX

    // ---- Epilogue: exp(-0.5*(dist+ck)) -> bf16 g_rbf ----------------------
    const int erow  = m0 + wm * 32 + (l >> 2);
    const int ecol0 = wn * 16 + 2 * (l & 3);
    #pragma unroll
    for (int nj = 0; nj < 2; nj++) {
        const int col = ecol0 + nj * 8;
        const float ck0 = g_ck[n0 + col];
        const float ck1 = g_ck[n0 + col + 1];
        #pragma unroll
        for (int mi = 0; mi < 2; mi++) {
            const int r = erow + mi * 16;
            float u0 = __expf(-0.5f * (acc[mi][nj][0] + ck0));
            float u1 = __expf(-0.5f * (acc[mi][nj][1] + ck1));
            float u2 = __expf(-0.5f * (acc[mi][nj][2] + ck0));
            float u3 = __expf(-0.5f * (acc[mi][nj][3] + ck1));
            __nv_bfloat162 p0 = __floats2bfloat162_rn(u0, u1);
            __nv_bfloat162 p1 = __floats2bfloat162_rn(u2, u3);
            *(__nv_bfloat162*)&g_rbf[(size_t)r * Kn + n0 + col]       = p0;
            *(__nv_bfloat162*)&g_rbf[(size_t)(r + 8) * Kn + n0 + col] = p1;
        }
    }
}

// ---------------------------------------------------------------------------
// G2 (unchanged from R8): h = rbf @ W^T via split-K HMMA; out = 1/(h+eps).
// C[64,64] = A[64,256] x B[64,256]^T, A=g_rbf, B=g_wt.
// ---------------------------------------------------------------------------
#define STAGE_BYTES 16384
#define NSTAGE 6
#define SMEMSZ (NSTAGE * STAGE_BYTES)   // 98304

__global__ void __launch_bounds__(256)
g2_kern(float* __restrict__ out) {
    constexpr int LD = 256, NSTEP = 2;
    const __nv_bfloat16* __restrict__ A  = g_rbf;
    const __nv_bfloat16* __restrict__ Bm = g_wt;

    extern __shared__ char sm[];
    const uint32_t T0 = s2u(sm);
    const int tid = threadIdx.x, wid = tid >> 5, l = tid & 31;
    const int m0 = blockIdx.x * 64, n0 = blockIdx.y * 64;
    const int grp = wid >> 2, wg = wid & 3;
    const int wm = wg & 1, wn = wg >> 1;

    const int lr = l & 7, sel = l >> 3;
    const int a_row = wm * 32 + (sel & 1) * 8 + lr;
    const uint32_t a_kb = (uint32_t)((sel >> 1) * 16);
    const int b_row = wn * 32 + (sel >> 1) * 8 + lr;
    const uint32_t b_kb = (uint32_t)((sel & 1) * 16);

    #define LOAD_CHUNK(ch) do {                                              \
        uint32_t _sa = T0 + ((ch) % NSTAGE) * STAGE_BYTES;                   \
        const __nv_bfloat16* _ga = A  + (size_t)m0 * LD + (ch) * 64;         \
        const __nv_bfloat16* _gb = Bm + (size_t)n0 * LD + (ch) * 64;         \
        _Pragma("unroll")                                                    \
        for (int q = 0; q < 2; q++) {                                        \
            int u = tid + q * 256;                                           \
            int r = u >> 3, cc = u & 7;                                      \
            uint32_t off = SW128((uint32_t)(r * 128 + cc * 16));             \
            cp16(_sa        + off, _ga + (size_t)r * LD + cc * 8);           \
            cp16(_sa + 8192 + off, _gb + (size_t)r * LD + cc * 8);           \
        }                                                                    \
    } while (0)

    #define LOAD_PAIR(p) do {                                                \
        LOAD_CHUNK(2 * (p));  LOAD_CHUNK(2 * (p) + 1);                       \
        asm volatile("cp.async.commit_group;");                              \
    } while (0)

    float acc[2][4][4];
    #pragma unroll
    for (int mi = 0; mi < 2; mi++)
        #pragma unroll
        for (int nj = 0; nj < 4; nj++)
            #pragma unroll
            for (int e = 0; e < 4; e++) acc[mi][nj][e] = 0.0f;

    LOAD_PAIR(0);
    LOAD_PAIR(1);

    for (int t = 0; t < NSTEP; t++) {
        if (t < NSTEP - 1) asm volatile("cp.async.wait_group 1;");
        else               asm volatile("cp.async.wait_group 0;");
        __syncthreads();

        const int ch = 2 * t + grp;
        const uint32_t sa  = T0 + (ch % NSTAGE) * STAGE_BYTES;
        const uint32_t sbb = sa + 8192;
        #pragma unroll
        for (int ks = 0; ks < 4; ks++) {
            uint32_t a[2][4], b[2][4];
            #pragma unroll
            for (int mi = 0; mi < 2; mi++)
                ldsm4(a[mi], sa + SW128((uint32_t)((a_row + mi * 16) * 128)
                                        + (uint32_t)(ks * 32) + a_kb));
            #pragma unroll
            for (int bi = 0; bi < 2; bi++)
                ldsm4(b[bi], sbb + SW128((uint32_t)((b_row + bi * 16) * 128)
                                         + (uint32_t)(ks * 32) + b_kb));
            #pragma unroll
            for (int mi = 0; mi < 2; mi++)
                #pragma unroll
                for (int nj = 0; nj < 4; nj++)
                    mma16816(acc[mi][nj], a[mi], &b[nj >> 1][(nj & 1) * 2]);
        }
    }
    #undef LOAD_PAIR
    #undef LOAD_CHUNK

    float* Rb = (float*)sm;
    const int rrow = wm * 32 + (l >> 2);
    const int rcol = wn * 32 + 2 * (l & 3);
    __syncthreads();
    if (grp == 1) {
        #pragma unroll
        for (int mi = 0; mi < 2; mi++)
            #pragma unroll
            for (int nj = 0; nj < 4; nj++) {
                const int r = rrow + mi * 16, c = rcol + nj * 8;
                *(float2*)&Rb[r * 72 + c]       = make_float2(acc[mi][nj][0], acc[mi][nj][1]);
                *(float2*)&Rb[(r + 8) * 72 + c] = make_float2(acc[mi][nj][2], acc[mi][nj][3]);
            }
    }
    __syncthreads();
    if (grp == 1) return;

    #pragma unroll
    for (int mi = 0; mi < 2; mi++)
        #pragma unroll
        for (int nj = 0; nj < 4; nj++) {
            const int r = rrow + mi * 16, c = rcol + nj * 8;
            float2 p0 = *(const float2*)&Rb[r * 72 + c];
            float2 p1 = *(const float2*)&Rb[(r + 8) * 72 + c];
            acc[mi][nj][0] += p0.x;  acc[mi][nj][1] += p0.y;
            acc[mi][nj][2] += p1.x;  acc[mi][nj][3] += p1.y;
        }

    const float eps = 1e-3f;
    const int erow = m0 + rrow;
    #pragma unroll
    for (int mi = 0; mi < 2; mi++) {
        #pragma unroll
        for (int nj = 0; nj < 4; nj++) {
            const int col = n0 + rcol + nj * 8;
            const int r = erow + mi * 16;
            float2 o0, o1;
            o0.x = __fdividef(1.0f, acc[mi][nj][0] + eps);
            o0.y = __fdividef(1.0f, acc[mi][nj][1] + eps);
            o1.x = __fdividef(1.0f, acc[mi][nj][2] + eps);
            o1.y = __fdividef(1.0f, acc[mi][nj][3] + eps);
            *(float2*)(out + (size_t)r * Dn + col)       = o0;
            *(float2*)(out + (size_t)(r + 8) * Dn + col) = o1;
        }
    }
}

// ---------------------------------------------------------------------------
extern "C" void kernel_launch(void* const* d_in, const int* in_sizes, int n_in,
                              void* d_out, int out_size) {
    const float* x           = (const float*)d_in[0];
    const float* centers     = (const float*)d_in[1];
    const float* bandwidths  = (const float*)d_in[2];
    const float* raw_weights = (const float*)d_in[3];
    float* out = (float*)d_out;

    static bool attr_set = false;
    if (!attr_set) {
        cudaFuncSetAttribute(g1_kern,
                             cudaFuncAttributeMaxDynamicSharedMemorySize, G1_SMEM);
        cudaFuncSetAttribute(g2_kern,
                             cudaFuncAttributeMaxDynamicSharedMemorySize, SMEMSZ);
        attr_set = true;
    }

    prep_all<<<160, 256>>>(centers, bandwidths, raw_weights);

    // G1: dist GEMM (M=2048, N=256, D=512 fused [x^2|x]) -> rbf (bf16)
    g1_kern<<<dim3(Bn / 64, Kn / 64), 256, G1_SMEM>>>(x);
    // G2: h GEMM (M=2048, N=512, K=256) -> out = 1/(h+eps)
    g2_kern<<<dim3(Bn / 64, Dn / 64), 256, SMEMSZ>>>(out);
}